// round 9
// baseline (speedup 1.0000x reference)
#include <cuda_runtime.h>
#include <cuda_bf16.h>
#include <math.h>
#include <stdint.h>

// Problem constants
constexpr int Bd = 2;
constexpr int Td = 2048;
constexpr int Cd = 1024;
constexpr int Hd = 16;
constexpr int Rows = Bd * Td;   // 4096
constexpr int QKVs = 3 * Cd;    // 3072

// ---------------- scratch (device globals) ---------------------------------
__device__ float g_h   [Rows * Cd];
__device__ float g_qkv [Rows * QKVs];
__device__ float g_P   [(size_t)Bd * Hd * Td * Td];
__device__ float g_attn[Rows * Cd];
__device__ float g_x1  [Rows * Cd];
__device__ float g_fc  [Rows * 4 * Cd];

// ---------------- bf16 mma m16n8k16 + split helpers ------------------------
__device__ __forceinline__ void mma_bf16(float* c, const uint32_t* a, const uint32_t* b) {
    asm volatile(
        "mma.sync.aligned.m16n8k16.row.col.f32.bf16.bf16.f32 "
        "{%0,%1,%2,%3}, {%4,%5,%6,%7}, {%8,%9}, {%0,%1,%2,%3};\n"
        : "+f"(c[0]), "+f"(c[1]), "+f"(c[2]), "+f"(c[3])
        : "r"(a[0]), "r"(a[1]), "r"(a[2]), "r"(a[3]), "r"(b[0]), "r"(b[1]));
}
__device__ __forceinline__ uint32_t packb(float even, float odd) {
    uint32_t r;
    asm("cvt.rn.bf16x2.f32 %0, %1, %2;" : "=r"(r) : "f"(odd), "f"(even));
    return r;
}
__device__ __forceinline__ void splitb(float x, float& hi, float& lo) {
    float h = __bfloat162float(__float2bfloat16_rn(x));
    hi = h; lo = x - h;
}
__device__ __forceinline__ void splitb4(float4 v, float4& hi, float4& lo) {
    splitb(v.x, hi.x, lo.x); splitb(v.y, hi.y, lo.y);
    splitb(v.z, hi.z, lo.z); splitb(v.w, hi.w, lo.w);
}

// ---------------- block reductions -----------------------------------------
__device__ __forceinline__ float block_reduce_sum(float v) {
    __shared__ float sm[32];
    int lane = threadIdx.x & 31, wid = threadIdx.x >> 5;
    #pragma unroll
    for (int o = 16; o; o >>= 1) v += __shfl_down_sync(0xffffffffu, v, o);
    if (lane == 0) sm[wid] = v;
    __syncthreads();
    float r;
    if (wid == 0) {
        float t = (lane < 8) ? sm[lane] : 0.0f;
        #pragma unroll
        for (int o = 4; o; o >>= 1) t += __shfl_down_sync(0xffu, t, o);
        if (lane == 0) sm[0] = t;
    }
    __syncthreads();
    r = sm[0];
    __syncthreads();
    return r;
}
__device__ __forceinline__ float block_reduce_max(float v) {
    __shared__ float sm[32];
    int lane = threadIdx.x & 31, wid = threadIdx.x >> 5;
    #pragma unroll
    for (int o = 16; o; o >>= 1) v = fmaxf(v, __shfl_down_sync(0xffffffffu, v, o));
    if (lane == 0) sm[wid] = v;
    __syncthreads();
    float r;
    if (wid == 0) {
        float t = (lane < 8) ? sm[lane] : -INFINITY;
        #pragma unroll
        for (int o = 4; o; o >>= 1) t = fmaxf(t, __shfl_down_sync(0xffu, t, o));
        if (lane == 0) sm[0] = t;
    }
    __syncthreads();
    r = sm[0];
    __syncthreads();
    return r;
}

// ---------------- LayerNorm ------------------------------------------------
__global__ __launch_bounds__(256) void ln_k(const float* __restrict__ x,
                                            const float* __restrict__ w,
                                            const float* __restrict__ b,
                                            float* __restrict__ y) {
    const int row = blockIdx.x;
    const float* xr = x + (size_t)row * Cd;
    float4 v = *(const float4*)(xr + threadIdx.x * 4);
    float s  = v.x + v.y + v.z + v.w;
    float sq = v.x * v.x + v.y * v.y + v.z * v.z + v.w * v.w;
    float sum  = block_reduce_sum(s);
    float sumq = block_reduce_sum(sq);
    float mean = sum * (1.0f / Cd);
    float var  = sumq * (1.0f / Cd) - mean * mean;
    float rstd = rsqrtf(var + 1e-5f);
    int c = threadIdx.x * 4;
    float4 wv = *(const float4*)(w + c);
    float4 bv = *(const float4*)(b + c);
    float4 o;
    o.x = (v.x - mean) * rstd * wv.x + bv.x;
    o.y = (v.y - mean) * rstd * wv.y + bv.y;
    o.z = (v.z - mean) * rstd * wv.z + bv.z;
    o.w = (v.w - mean) * rstd * wv.w + bv.w;
    *(float4*)(y + (size_t)row * Cd + c) = o;
}

// ---------------- 3xBF16 GEMM, BK=32, split-in-kernel, reg prefetch --------
// C[M,N] = A[M,K] @ B[K,N] + bias; EPI: 0 bias, 1 bias+res, 2 gelu(bias+.)
template <int EPI>
__global__ __launch_bounds__(256, 2) void tgemm_k(int M, int N, int K,
                                                  const float* __restrict__ A,
                                                  const float* __restrict__ B,
                                                  const float* __restrict__ bias,
                                                  const float* __restrict__ res,
                                                  float* __restrict__ C) {
    constexpr int BK = 32;
    __shared__ uint32_t Ah[128][20], Al[128][20];   // 16 data u32 + 4 pad
    __shared__ uint32_t Bh[16][136], Bl[16][136];   // 128 data + 8 pad
    const int tid = threadIdx.x, lane = tid & 31, warp = tid >> 5;
    const int warpM = warp >> 2, warpN = warp & 3;  // 2 x 4 warps
    const size_t bM = (size_t)blockIdx.y * 128, bN = (size_t)blockIdx.x * 128;

    const int aRow = tid >> 1, aHalf = (tid & 1) * 16;  // A: row, 16-float half
    const int bKp = tid >> 4, bN8 = (tid & 15) * 8;     // B: k-pair row, 8-n group

    float4 ra[4], rb[2][2];
    #pragma unroll
    for (int j = 0; j < 4; j++)
        ra[j] = *(const float4*)(A + (bM + aRow) * (size_t)K + aHalf + 4 * j);
    #pragma unroll
    for (int g = 0; g < 2; g++) {
        rb[g][0] = *(const float4*)(B + (size_t)(2 * bKp) * N + bN + bN8 + 4 * g);
        rb[g][1] = *(const float4*)(B + (size_t)(2 * bKp + 1) * N + bN + bN8 + 4 * g);
    }

    float acc[4][4][4] = {};
    const int nch = K / BK;
    for (int c = 0; c < nch; c++) {
        // ---- stage current regs (split fp32 -> packed bf16 hi/lo) ----------
        #pragma unroll
        for (int j = 0; j < 4; j++) {
            float4 h, l; splitb4(ra[j], h, l);
            int col = (aHalf >> 1) + 2 * j;
            *(uint2*)&Ah[aRow][col] = make_uint2(packb(h.x, h.y), packb(h.z, h.w));
            *(uint2*)&Al[aRow][col] = make_uint2(packb(l.x, l.y), packb(l.z, l.w));
        }
        #pragma unroll
        for (int g = 0; g < 2; g++) {
            float4 h0, l0, h1, l1;
            splitb4(rb[g][0], h0, l0); splitb4(rb[g][1], h1, l1);
            *(uint4*)&Bh[bKp][bN8 + 4 * g] = make_uint4(packb(h0.x, h1.x), packb(h0.y, h1.y),
                                                        packb(h0.z, h1.z), packb(h0.w, h1.w));
            *(uint4*)&Bl[bKp][bN8 + 4 * g] = make_uint4(packb(l0.x, l1.x), packb(l0.y, l1.y),
                                                        packb(l0.z, l1.z), packb(l0.w, l1.w));
        }
        __syncthreads();
        // ---- prefetch next chunk ------------------------------------------
        if (c + 1 < nch) {
            #pragma unroll
            for (int j = 0; j < 4; j++)
                ra[j] = *(const float4*)(A + (bM + aRow) * (size_t)K + (c + 1) * BK + aHalf + 4 * j);
            #pragma unroll
            for (int g = 0; g < 2; g++) {
                rb[g][0] = *(const float4*)(B + (size_t)((c + 1) * BK + 2 * bKp) * N + bN + bN8 + 4 * g);
                rb[g][1] = *(const float4*)(B + (size_t)((c + 1) * BK + 2 * bKp + 1) * N + bN + bN8 + 4 * g);
            }
        }
        // ---- compute: two k16 steps ---------------------------------------
        #pragma unroll
        for (int ks = 0; ks < 2; ks++) {
            const int kb0 = ks * 8 + (lane & 3), fr = lane >> 2;
            uint32_t a_h[4][4], a_l[4][4], b_h[4][2], b_l[4][2];
            #pragma unroll
            for (int mt = 0; mt < 4; mt++) {
                int r = warpM * 64 + mt * 16 + fr;
                a_h[mt][0] = Ah[r][kb0];     a_h[mt][1] = Ah[r + 8][kb0];
                a_h[mt][2] = Ah[r][kb0 + 4]; a_h[mt][3] = Ah[r + 8][kb0 + 4];
                a_l[mt][0] = Al[r][kb0];     a_l[mt][1] = Al[r + 8][kb0];
                a_l[mt][2] = Al[r][kb0 + 4]; a_l[mt][3] = Al[r + 8][kb0 + 4];
            }
            #pragma unroll
            for (int nt = 0; nt < 4; nt++) {
                int n = warpN * 32 + nt * 8 + fr;
                b_h[nt][0] = Bh[kb0][n]; b_h[nt][1] = Bh[kb0 + 4][n];
                b_l[nt][0] = Bl[kb0][n]; b_l[nt][1] = Bl[kb0 + 4][n];
            }
            #pragma unroll
            for (int mt = 0; mt < 4; mt++)
                #pragma unroll
                for (int nt = 0; nt < 4; nt++) {
                    mma_bf16(acc[mt][nt], a_l[mt], b_h[nt]);
                    mma_bf16(acc[mt][nt], a_h[mt], b_l[nt]);
                    mma_bf16(acc[mt][nt], a_h[mt], b_h[nt]);
                }
        }
        __syncthreads();
    }
    // epilogue
    #pragma unroll
    for (int mt = 0; mt < 4; mt++) {
        #pragma unroll
        for (int nt = 0; nt < 4; nt++) {
            size_t r0 = bM + warpM * 64 + mt * 16 + (lane >> 2);
            size_t cb = bN + warpN * 32 + nt * 8 + (lane & 3) * 2;
            float b0 = bias[cb], b1 = bias[cb + 1];
            #pragma unroll
            for (int half = 0; half < 2; half++) {
                size_t r = r0 + half * 8;
                float v0 = acc[mt][nt][half * 2 + 0] + b0;
                float v1 = acc[mt][nt][half * 2 + 1] + b1;
                if (EPI == 1) {
                    const float* rp = res + r * N + cb;
                    v0 += rp[0]; v1 += rp[1];
                }
                if (EPI == 2) {
                    v0 = 0.5f * v0 * (1.0f + erff(v0 * 0.70710678118654752f));
                    v1 = 0.5f * v1 * (1.0f + erff(v1 * 0.70710678118654752f));
                }
                *(float2*)(C + r * N + cb) = make_float2(v0, v1);
            }
        }
    }
}

// ---------------- scores: S = Q K^T * scale (lower blocks), 3xBF16 ---------
__global__ __launch_bounds__(128) void scores_tc(const float* __restrict__ qkv,
                                                 float* __restrict__ P) {
    const int bh = blockIdx.z;
    const int b = bh >> 4, h = bh & 15;
    const int t0 = blockIdx.y * 64, s0 = blockIdx.x * 64;
    if (s0 > t0) return;
    __shared__ uint32_t Qh[64][36], Ql[64][36];
    __shared__ uint32_t Kh[64][36], Kl[64][36];
    const int tid = threadIdx.x, lane = tid & 31, warp = tid >> 5;
    const int warpM = warp >> 1, warpN = warp & 1;
    const float* qb = qkv + (size_t)(b * Td + t0) * QKVs + h * 64;
    const float* kb = qkv + (size_t)(b * Td + s0) * QKVs + Cd + h * 64;
    #pragma unroll
    for (int i = 0; i < 8; i++) {
        int idx = tid + i * 128;
        int r = idx >> 4, c4 = (idx & 15) * 4;
        float4 hi, lo;
        splitb4(*(const float4*)(qb + (size_t)r * QKVs + c4), hi, lo);
        *(uint2*)&Qh[r][c4 >> 1] = make_uint2(packb(hi.x, hi.y), packb(hi.z, hi.w));
        *(uint2*)&Ql[r][c4 >> 1] = make_uint2(packb(lo.x, lo.y), packb(lo.z, lo.w));
        splitb4(*(const float4*)(kb + (size_t)r * QKVs + c4), hi, lo);
        *(uint2*)&Kh[r][c4 >> 1] = make_uint2(packb(hi.x, hi.y), packb(hi.z, hi.w));
        *(uint2*)&Kl[r][c4 >> 1] = make_uint2(packb(lo.x, lo.y), packb(lo.z, lo.w));
    }
    __syncthreads();
    float acc[2][4][4] = {};
    #pragma unroll
    for (int ks = 0; ks < 4; ks++) {
        const int kb0 = ks * 8 + (lane & 3), fr = lane >> 2;
        uint32_t a_h[2][4], a_l[2][4], b_h[4][2], b_l[4][2];
        #pragma unroll
        for (int mt = 0; mt < 2; mt++) {
            int r = warpM * 32 + mt * 16 + fr;
            a_h[mt][0] = Qh[r][kb0];     a_h[mt][1] = Qh[r + 8][kb0];
            a_h[mt][2] = Qh[r][kb0 + 4]; a_h[mt][3] = Qh[r + 8][kb0 + 4];
            a_l[mt][0] = Ql[r][kb0];     a_l[mt][1] = Ql[r + 8][kb0];
            a_l[mt][2] = Ql[r][kb0 + 4]; a_l[mt][3] = Ql[r + 8][kb0 + 4];
        }
        #pragma unroll
        for (int nt = 0; nt < 4; nt++) {
            int n = warpN * 32 + nt * 8 + fr;
            b_h[nt][0] = Kh[n][kb0]; b_h[nt][1] = Kh[n][kb0 + 4];
            b_l[nt][0] = Kl[n][kb0]; b_l[nt][1] = Kl[n][kb0 + 4];
        }
        #pragma unroll
        for (int mt = 0; mt < 2; mt++)
            #pragma unroll
            for (int nt = 0; nt < 4; nt++) {
                mma_bf16(acc[mt][nt], a_l[mt], b_h[nt]);
                mma_bf16(acc[mt][nt], a_h[mt], b_l[nt]);
                mma_bf16(acc[mt][nt], a_h[mt], b_h[nt]);
            }
    }
    const float scale = 0.125f;
    #pragma unroll
    for (int mt = 0; mt < 2; mt++) {
        #pragma unroll
        for (int nt = 0; nt < 4; nt++) {
            int r0 = t0 + warpM * 32 + mt * 16 + (lane >> 2);
            int cb = s0 + warpN * 32 + nt * 8 + (lane & 3) * 2;
            #pragma unroll
            for (int half = 0; half < 2; half++) {
                int r = r0 + half * 8;
                float2 o = make_float2(acc[mt][nt][half * 2] * scale,
                                       acc[mt][nt][half * 2 + 1] * scale);
                *(float2*)(P + ((size_t)bh * Td + r) * Td + cb) = o;
            }
        }
    }
}

// ---------------- causal softmax per row (float4, smem buffer) --------------
__global__ __launch_bounds__(256) void softmax_k(float* __restrict__ P) {
    __shared__ float buf[Td];
    const size_t r = blockIdx.x;
    const int t = (int)(r & (Td - 1));
    float* row = P + r * Td;
    const int n = t + 1, n4 = n >> 2, tail = n4 * 4;
    float4* row4 = (float4*)row;
    float4* buf4 = (float4*)buf;
    float m = -INFINITY;
    for (int i = threadIdx.x; i < n4; i += 256) {
        float4 v = row4[i];
        buf4[i] = v;
        m = fmaxf(m, fmaxf(fmaxf(v.x, v.y), fmaxf(v.z, v.w)));
    }
    {
        int i = tail + threadIdx.x;
        if (i < n) { float v = row[i]; buf[i] = v; m = fmaxf(m, v); }
    }
    m = block_reduce_max(m);
    float s = 0.0f;
    for (int i = threadIdx.x; i < n4; i += 256) {
        float4 v = buf4[i];
        v.x = __expf(v.x - m); v.y = __expf(v.y - m);
        v.z = __expf(v.z - m); v.w = __expf(v.w - m);
        buf4[i] = v;
        s += v.x + v.y + v.z + v.w;
    }
    {
        int i = tail + threadIdx.x;
        if (i < n) { float e = __expf(buf[i] - m); buf[i] = e; s += e; }
    }
    s = block_reduce_sum(s);
    const float inv = 1.0f / s;
    for (int i = threadIdx.x; i < n4; i += 256) {
        float4 v = buf4[i];
        v.x *= inv; v.y *= inv; v.z *= inv; v.w *= inv;
        row4[i] = v;
    }
    {
        int i = tail + threadIdx.x;
        if (i < n) row[i] = buf[i] * inv;
    }
    const int fillEnd = ((t >> 6) << 6) + 64;
    for (int i = n + (int)threadIdx.x; i < fillEnd; i += 256) row[i] = 0.0f;
}

// ---------------- attn_mean ------------------------------------------------
__global__ __launch_bounds__(256) void attnmean_k(const float* __restrict__ P,
                                                  float* __restrict__ out) {
    const size_t i4 = (size_t)blockIdx.x * 256 + threadIdx.x;
    const int scol = (int)(i4 & (Td / 4 - 1)) * 4;
    const int t = (int)((i4 >> 9) & (Td - 1));
    const size_t off = (size_t)Hd * Td * Td;
    float4 o;
    if (scol > t) {
        o = make_float4(0.f, 0.f, 0.f, 0.f);
    } else {
        float4 a = *(const float4*)(P + i4 * 4);
        float4 b = *(const float4*)(P + i4 * 4 + off);
        o.x = 0.5f * (a.x + b.x); o.y = 0.5f * (a.y + b.y);
        o.z = 0.5f * (a.z + b.z); o.w = 0.5f * (a.w + b.w);
    }
    *(float4*)(out + i4 * 4) = o;
}

// ---------------- attn_out = P @ V (triangular), 3xBF16 --------------------
__global__ __launch_bounds__(128) void pv_tc(const float* __restrict__ P,
                                             const float* __restrict__ qkv,
                                             float* __restrict__ out) {
    const int bh = blockIdx.y;
    const int b = bh >> 4, h = bh & 15;
    const int t0 = blockIdx.x * 64;
    __shared__ uint32_t Ph[64][36], Pl[64][36];
    __shared__ uint32_t Vh[32][72], Vl[32][72];
    const int tid = threadIdx.x, lane = tid & 31, warp = tid >> 5;
    const int warpM = warp >> 1, warpN = warp & 1;
    float acc[2][4][4] = {};
    for (int s0 = 0; s0 <= t0; s0 += 64) {
        #pragma unroll
        for (int i = 0; i < 8; i++) {
            int idx = tid + i * 128;
            int r = idx >> 4, c4 = (idx & 15) * 4;
            float4 hi, lo;
            splitb4(*(const float4*)(P + ((size_t)bh * Td + t0 + r) * Td + s0 + c4), hi, lo);
            *(uint2*)&Ph[r][c4 >> 1] = make_uint2(packb(hi.x, hi.y), packb(hi.z, hi.w));
            *(uint2*)&Pl[r][c4 >> 1] = make_uint2(packb(lo.x, lo.y), packb(lo.z, lo.w));
        }
        #pragma unroll
        for (int i = 0; i < 4; i++) {
            int idx = tid + i * 128;
            int kkr = idx >> 4, n4 = (idx & 15) * 4;
            const float* vb = qkv + (size_t)(b * Td + s0) * QKVs + 2 * Cd + h * 64;
            float4 hA, lA, hB, lB;
            splitb4(*(const float4*)(vb + (size_t)(2 * kkr) * QKVs + n4), hA, lA);
            splitb4(*(const float4*)(vb + (size_t)(2 * kkr + 1) * QKVs + n4), hB, lB);
            *(uint4*)&Vh[kkr][n4] = make_uint4(packb(hA.x, hB.x), packb(hA.y, hB.y),
                                               packb(hA.z, hB.z), packb(hA.w, hB.w));
            *(uint4*)&Vl[kkr][n4] = make_uint4(packb(lA.x, lB.x), packb(lA.y, lB.y),
                                               packb(lA.z, lB.z), packb(lA.w, lB.w));
        }
        __syncthreads();
        #pragma unroll
        for (int ks = 0; ks < 4; ks++) {
            const int kb0 = ks * 8 + (lane & 3), fr = lane >> 2;
            uint32_t a_h[2][4], a_l[2][4], b_h[4][2], b_l[4][2];
            #pragma unroll
            for (int mt = 0; mt < 2; mt++) {
                int r = warpM * 32 + mt * 16 + fr;
                a_h[mt][0] = Ph[r][kb0];     a_h[mt][1] = Ph[r + 8][kb0];
                a_h[mt][2] = Ph[r][kb0 + 4]; a_h[mt][3] = Ph[r + 8][kb0 + 4];
                a_l[mt][0] = Pl[r][kb0];     a_l[mt][1] = Pl[r + 8][kb0];
                a_l[mt][2] = Pl[r][kb0 + 4]; a_l[mt][3] = Pl[r + 8][kb0 + 4];
            }
            #pragma unroll
            for (int nt = 0; nt < 4; nt++) {
                int n = warpN * 32 + nt * 8 + fr;
                b_h[nt][0] = Vh[kb0][n]; b_h[nt][1] = Vh[kb0 + 4][n];
                b_l[nt][0] = Vl[kb0][n]; b_l[nt][1] = Vl[kb0 + 4][n];
            }
            #pragma unroll
            for (int mt = 0; mt < 2; mt++)
                #pragma unroll
                for (int nt = 0; nt < 4; nt++) {
                    mma_bf16(acc[mt][nt], a_l[mt], b_h[nt]);
                    mma_bf16(acc[mt][nt], a_h[mt], b_l[nt]);
                    mma_bf16(acc[mt][nt], a_h[mt], b_h[nt]);
                }
        }
        __syncthreads();
    }
    #pragma unroll
    for (int mt = 0; mt < 2; mt++) {
        #pragma unroll
        for (int nt = 0; nt < 4; nt++) {
            int r0 = t0 + warpM * 32 + mt * 16 + (lane >> 2);
            int cb = warpN * 32 + nt * 8 + (lane & 3) * 2;
            #pragma unroll
            for (int half = 0; half < 2; half++) {
                int r = r0 + half * 8;
                float2 o = make_float2(acc[mt][nt][half * 2], acc[mt][nt][half * 2 + 1]);
                *(float2*)(out + (size_t)(b * Td + r) * Cd + h * 64 + cb) = o;
            }
        }
    }
}

// ---------------- launch ---------------------------------------------------
extern "C" void kernel_launch(void* const* d_in, const int* in_sizes, int n_in,
                              void* d_out, int out_size) {
    const float* x      = (const float*)d_in[0];
    const float* ln1_w  = (const float*)d_in[1];
    const float* ln1_b  = (const float*)d_in[2];
    const float* w_qkv  = (const float*)d_in[3];
    const float* b_qkv  = (const float*)d_in[4];
    const float* w_proj = (const float*)d_in[5];
    const float* b_proj = (const float*)d_in[6];
    const float* ln2_w  = (const float*)d_in[7];
    const float* ln2_b  = (const float*)d_in[8];
    const float* w_fc   = (const float*)d_in[9];
    const float* b_fc   = (const float*)d_in[10];
    const float* w_fc2  = (const float*)d_in[11];
    const float* b_fc2  = (const float*)d_in[12];

    float* out_x    = (float*)d_out;
    float* out_attn = (float*)d_out + (size_t)Rows * Cd;

    float *gh, *gqkv, *gP, *gattn, *gx1, *gfc;
    cudaGetSymbolAddress((void**)&gh,   g_h);
    cudaGetSymbolAddress((void**)&gqkv, g_qkv);
    cudaGetSymbolAddress((void**)&gP,   g_P);
    cudaGetSymbolAddress((void**)&gattn,g_attn);
    cudaGetSymbolAddress((void**)&gx1,  g_x1);
    cudaGetSymbolAddress((void**)&gfc,  g_fc);

    ln_k<<<Rows, 256>>>(x, ln1_w, ln1_b, gh);
    tgemm_k<0><<<dim3(QKVs / 128, Rows / 128), 256>>>(Rows, QKVs, Cd, gh, w_qkv, b_qkv, nullptr, gqkv);
    scores_tc<<<dim3(Td / 64, Td / 64, Bd * Hd), 128>>>(gqkv, gP);
    softmax_k<<<Bd * Hd * Td, 256>>>(gP);
    attnmean_k<<<(unsigned)((size_t)Hd * Td * Td / 4 / 256), 256>>>(gP, out_attn);
    pv_tc<<<dim3(Td / 64, Bd * Hd), 128>>>(gP, gqkv, gattn);
    tgemm_k<1><<<dim3(Cd / 128, Rows / 128), 256>>>(Rows, Cd, Cd, gattn, w_proj, b_proj, x, gx1);
    ln_k<<<Rows, 256>>>(gx1, ln2_w, ln2_b, gh);
    tgemm_k<2><<<dim3(4 * Cd / 128, Rows / 128), 256>>>(Rows, 4 * Cd, Cd, gh, w_fc, b_fc, nullptr, gfc);
    tgemm_k<1><<<dim3(Cd / 128, Rows / 128), 256>>>(Rows, Cd, 4 * Cd, gfc, w_fc2, b_fc2, gx1, out_x);
}

// round 11
// speedup vs baseline: 1.3181x; 1.3181x over previous
#include <cuda_runtime.h>
#include <cuda_bf16.h>
#include <math.h>
#include <stdint.h>

// Problem constants
constexpr int Bd = 2;
constexpr int Td = 2048;
constexpr int Cd = 1024;
constexpr int Hd = 16;
constexpr int Rows = Bd * Td;   // 4096
constexpr int QKVs = 3 * Cd;    // 3072

// ---------------- scratch (device globals) ---------------------------------
__device__ float g_h   [Rows * Cd];
__device__ float g_qkv [Rows * QKVs];
__device__ float g_P   [(size_t)Bd * Hd * Td * Td];
__device__ float g_attn[Rows * Cd];
__device__ float g_x1  [Rows * Cd];
__device__ float g_fc  [Rows * 4 * Cd];

// ---------------- bf16 mma m16n8k16 + split helpers ------------------------
__device__ __forceinline__ void mma_bf16(float* c, const uint32_t* a, const uint32_t* b) {
    asm volatile(
        "mma.sync.aligned.m16n8k16.row.col.f32.bf16.bf16.f32 "
        "{%0,%1,%2,%3}, {%4,%5,%6,%7}, {%8,%9}, {%0,%1,%2,%3};\n"
        : "+f"(c[0]), "+f"(c[1]), "+f"(c[2]), "+f"(c[3])
        : "r"(a[0]), "r"(a[1]), "r"(a[2]), "r"(a[3]), "r"(b[0]), "r"(b[1]));
}
__device__ __forceinline__ uint32_t packb(float even, float odd) {
    uint32_t r;
    asm("cvt.rn.bf16x2.f32 %0, %1, %2;" : "=r"(r) : "f"(odd), "f"(even));
    return r;
}
__device__ __forceinline__ void splitb(float x, float& hi, float& lo) {
    float h = __bfloat162float(__float2bfloat16_rn(x));
    hi = h; lo = x - h;
}
__device__ __forceinline__ void splitb4(float4 v, float4& hi, float4& lo) {
    splitb(v.x, hi.x, lo.x); splitb(v.y, hi.y, lo.y);
    splitb(v.z, hi.z, lo.z); splitb(v.w, hi.w, lo.w);
}
// ldmatrix x4: loads a full m16k16 bf16 A-fragment (4 regs) in one instr
__device__ __forceinline__ void ldsm_x4(uint32_t* r, uint32_t addr) {
    asm volatile("ldmatrix.sync.aligned.m8n8.x4.shared.b16 {%0,%1,%2,%3}, [%4];"
                 : "=r"(r[0]), "=r"(r[1]), "=r"(r[2]), "=r"(r[3]) : "r"(addr));
}

// ---------------- block reductions -----------------------------------------
__device__ __forceinline__ float block_reduce_sum(float v) {
    __shared__ float sm[32];
    int lane = threadIdx.x & 31, wid = threadIdx.x >> 5;
    #pragma unroll
    for (int o = 16; o; o >>= 1) v += __shfl_down_sync(0xffffffffu, v, o);
    if (lane == 0) sm[wid] = v;
    __syncthreads();
    float r;
    if (wid == 0) {
        float t = (lane < 8) ? sm[lane] : 0.0f;
        #pragma unroll
        for (int o = 4; o; o >>= 1) t += __shfl_down_sync(0xffu, t, o);
        if (lane == 0) sm[0] = t;
    }
    __syncthreads();
    r = sm[0];
    __syncthreads();
    return r;
}
__device__ __forceinline__ float block_reduce_max(float v) {
    __shared__ float sm[32];
    int lane = threadIdx.x & 31, wid = threadIdx.x >> 5;
    #pragma unroll
    for (int o = 16; o; o >>= 1) v = fmaxf(v, __shfl_down_sync(0xffffffffu, v, o));
    if (lane == 0) sm[wid] = v;
    __syncthreads();
    float r;
    if (wid == 0) {
        float t = (lane < 8) ? sm[lane] : -INFINITY;
        #pragma unroll
        for (int o = 4; o; o >>= 1) t = fmaxf(t, __shfl_down_sync(0xffu, t, o));
        if (lane == 0) sm[0] = t;
    }
    __syncthreads();
    r = sm[0];
    __syncthreads();
    return r;
}

// ---------------- LayerNorm ------------------------------------------------
__global__ __launch_bounds__(256) void ln_k(const float* __restrict__ x,
                                            const float* __restrict__ w,
                                            const float* __restrict__ b,
                                            float* __restrict__ y) {
    const int row = blockIdx.x;
    const float* xr = x + (size_t)row * Cd;
    float4 v = *(const float4*)(xr + threadIdx.x * 4);
    float s  = v.x + v.y + v.z + v.w;
    float sq = v.x * v.x + v.y * v.y + v.z * v.z + v.w * v.w;
    float sum  = block_reduce_sum(s);
    float sumq = block_reduce_sum(sq);
    float mean = sum * (1.0f / Cd);
    float var  = sumq * (1.0f / Cd) - mean * mean;
    float rstd = rsqrtf(var + 1e-5f);
    int c = threadIdx.x * 4;
    float4 wv = *(const float4*)(w + c);
    float4 bv = *(const float4*)(b + c);
    float4 o;
    o.x = (v.x - mean) * rstd * wv.x + bv.x;
    o.y = (v.y - mean) * rstd * wv.y + bv.y;
    o.z = (v.z - mean) * rstd * wv.z + bv.z;
    o.w = (v.w - mean) * rstd * wv.w + bv.w;
    *(float4*)(y + (size_t)row * Cd + c) = o;
}

// ---------------- 3xBF16 GEMM (R6 structure + LDSM A-fragments) ------------
// C[M,N] = A[M,K] @ B[K,N] + bias; EPI: 0 bias, 1 bias+res, 2 gelu(bias+.)
template <int EPI>
__global__ __launch_bounds__(256) void tgemm_k(int M, int N, int K,
                                               const float* __restrict__ A,
                                               const float* __restrict__ B,
                                               const float* __restrict__ bias,
                                               const float* __restrict__ res,
                                               float* __restrict__ C) {
    constexpr int BK = 16;
    __shared__ uint32_t Ah[128][12], Al[128][12];   // 8 data u32 + 4 pad (stride 12)
    __shared__ uint32_t Bh[8][136],  Bl[8][136];    // kk rows, 128 n + 8 pad
    const int tid = threadIdx.x, lane = tid & 31, warp = tid >> 5;
    const int warpM = warp >> 2, warpN = warp & 3;  // 2 x 4 warps
    const size_t bM = (size_t)blockIdx.y * 128, bN = (size_t)blockIdx.x * 128;

    const int aRow = tid >> 2, aC = (tid & 3) * 4;  // A: rows aRow, aRow+64; k cols aC..aC+3
    const int bK = warp * 2;                        // B: k rows bK, bK+1
    const int bCol = lane * 4;                      // n cols

    // ldmatrix source addresses (row = lane&15, 16B half = lane>>4)
    const uint32_t aHbase = (uint32_t)__cvta_generic_to_shared(&Ah[0][0]);
    const uint32_t aLbase = (uint32_t)__cvta_generic_to_shared(&Al[0][0]);
    const int ldsmRow = (lane & 15), ldsmCol = (lane >> 4) * 4;

    float4 ra[2], rba, rbb;
    #pragma unroll
    for (int i = 0; i < 2; i++)
        ra[i] = *(const float4*)(A + (bM + aRow + 64 * i) * (size_t)K + aC);
    rba = *(const float4*)(B + (size_t)bK * N + bN + bCol);
    rbb = *(const float4*)(B + (size_t)(bK + 1) * N + bN + bCol);

    float acc[4][4][4] = {};
    for (int k0 = 0; k0 < K; k0 += BK) {
        // split current regs into hi/lo packed smem tiles (R6 mapping)
        #pragma unroll
        for (int i = 0; i < 2; i++) {
            float4 hi, lo;
            splitb4(ra[i], hi, lo);
            *(uint2*)&Ah[aRow + 64 * i][(tid & 3) * 2] =
                make_uint2(packb(hi.x, hi.y), packb(hi.z, hi.w));
            *(uint2*)&Al[aRow + 64 * i][(tid & 3) * 2] =
                make_uint2(packb(lo.x, lo.y), packb(lo.z, lo.w));
        }
        {
            float4 ha, la, hb, lb;
            splitb4(rba, ha, la);
            splitb4(rbb, hb, lb);
            *(uint4*)&Bh[warp][bCol] = make_uint4(packb(ha.x, hb.x), packb(ha.y, hb.y),
                                                  packb(ha.z, hb.z), packb(ha.w, hb.w));
            *(uint4*)&Bl[warp][bCol] = make_uint4(packb(la.x, lb.x), packb(la.y, lb.y),
                                                  packb(la.z, lb.z), packb(la.w, lb.w));
        }
        __syncthreads();
        if (k0 + BK < K) {
            #pragma unroll
            for (int i = 0; i < 2; i++)
                ra[i] = *(const float4*)(A + (bM + aRow + 64 * i) * (size_t)K + k0 + BK + aC);
            rba = *(const float4*)(B + (size_t)(k0 + BK + bK) * N + bN + bCol);
            rbb = *(const float4*)(B + (size_t)(k0 + BK + bK + 1) * N + bN + bCol);
        }
        // single k16 step covers BK
        uint32_t a_h[4][4], a_l[4][4], b_h[4][2], b_l[4][2];
        const int kk = lane & 3, fr = lane >> 2;
        #pragma unroll
        for (int mt = 0; mt < 4; mt++) {
            int r = warpM * 64 + mt * 16 + ldsmRow;
            ldsm_x4(a_h[mt], aHbase + (uint32_t)(r * 12 + ldsmCol) * 4u);
            ldsm_x4(a_l[mt], aLbase + (uint32_t)(r * 12 + ldsmCol) * 4u);
        }
        #pragma unroll
        for (int nt = 0; nt < 4; nt++) {
            int n = warpN * 32 + nt * 8 + fr;
            b_h[nt][0] = Bh[kk][n]; b_h[nt][1] = Bh[kk + 4][n];
            b_l[nt][0] = Bl[kk][n]; b_l[nt][1] = Bl[kk + 4][n];
        }
        #pragma unroll
        for (int mt = 0; mt < 4; mt++)
            #pragma unroll
            for (int nt = 0; nt < 4; nt++) {
                mma_bf16(acc[mt][nt], a_l[mt], b_h[nt]);
                mma_bf16(acc[mt][nt], a_h[mt], b_l[nt]);
                mma_bf16(acc[mt][nt], a_h[mt], b_h[nt]);
            }
        __syncthreads();
    }
    // epilogue
    #pragma unroll
    for (int mt = 0; mt < 4; mt++) {
        #pragma unroll
        for (int nt = 0; nt < 4; nt++) {
            size_t r0 = bM + warpM * 64 + mt * 16 + (lane >> 2);
            size_t cb = bN + warpN * 32 + nt * 8 + (lane & 3) * 2;
            float b0 = bias[cb], b1 = bias[cb + 1];
            #pragma unroll
            for (int half = 0; half < 2; half++) {
                size_t r = r0 + half * 8;
                float v0 = acc[mt][nt][half * 2 + 0] + b0;
                float v1 = acc[mt][nt][half * 2 + 1] + b1;
                if (EPI == 1) {
                    const float* rp = res + r * N + cb;
                    v0 += rp[0]; v1 += rp[1];
                }
                if (EPI == 2) {
                    v0 = 0.5f * v0 * (1.0f + erff(v0 * 0.70710678118654752f));
                    v1 = 0.5f * v1 * (1.0f + erff(v1 * 0.70710678118654752f));
                }
                *(float2*)(C + r * N + cb) = make_float2(v0, v1);
            }
        }
    }
}

// ---------------- scores: S = Q K^T * scale (lower blocks), 3xBF16 ---------
__global__ __launch_bounds__(128) void scores_tc(const float* __restrict__ qkv,
                                                 float* __restrict__ P) {
    const int bh = blockIdx.z;
    const int b = bh >> 4, h = bh & 15;
    const int t0 = blockIdx.y * 64, s0 = blockIdx.x * 64;
    if (s0 > t0) return;
    __shared__ uint32_t Qh[64][36], Ql[64][36];
    __shared__ uint32_t Kh[64][36], Kl[64][36];
    const int tid = threadIdx.x, lane = tid & 31, warp = tid >> 5;
    const int warpM = warp >> 1, warpN = warp & 1;
    const float* qb = qkv + (size_t)(b * Td + t0) * QKVs + h * 64;
    const float* kb = qkv + (size_t)(b * Td + s0) * QKVs + Cd + h * 64;
    #pragma unroll
    for (int i = 0; i < 8; i++) {
        int idx = tid + i * 128;
        int r = idx >> 4, c4 = (idx & 15) * 4;
        float4 hi, lo;
        splitb4(*(const float4*)(qb + (size_t)r * QKVs + c4), hi, lo);
        *(uint2*)&Qh[r][c4 >> 1] = make_uint2(packb(hi.x, hi.y), packb(hi.z, hi.w));
        *(uint2*)&Ql[r][c4 >> 1] = make_uint2(packb(lo.x, lo.y), packb(lo.z, lo.w));
        splitb4(*(const float4*)(kb + (size_t)r * QKVs + c4), hi, lo);
        *(uint2*)&Kh[r][c4 >> 1] = make_uint2(packb(hi.x, hi.y), packb(hi.z, hi.w));
        *(uint2*)&Kl[r][c4 >> 1] = make_uint2(packb(lo.x, lo.y), packb(lo.z, lo.w));
    }
    __syncthreads();
    float acc[2][4][4] = {};
    #pragma unroll
    for (int ks = 0; ks < 4; ks++) {
        const int kb0 = ks * 8 + (lane & 3), fr = lane >> 2;
        uint32_t a_h[2][4], a_l[2][4], b_h[4][2], b_l[4][2];
        #pragma unroll
        for (int mt = 0; mt < 2; mt++) {
            int r = warpM * 32 + mt * 16 + fr;
            a_h[mt][0] = Qh[r][kb0];     a_h[mt][1] = Qh[r + 8][kb0];
            a_h[mt][2] = Qh[r][kb0 + 4]; a_h[mt][3] = Qh[r + 8][kb0 + 4];
            a_l[mt][0] = Ql[r][kb0];     a_l[mt][1] = Ql[r + 8][kb0];
            a_l[mt][2] = Ql[r][kb0 + 4]; a_l[mt][3] = Ql[r + 8][kb0 + 4];
        }
        #pragma unroll
        for (int nt = 0; nt < 4; nt++) {
            int n = warpN * 32 + nt * 8 + fr;
            b_h[nt][0] = Kh[n][kb0]; b_h[nt][1] = Kh[n][kb0 + 4];
            b_l[nt][0] = Kl[n][kb0]; b_l[nt][1] = Kl[n][kb0 + 4];
        }
        #pragma unroll
        for (int mt = 0; mt < 2; mt++)
            #pragma unroll
            for (int nt = 0; nt < 4; nt++) {
                mma_bf16(acc[mt][nt], a_l[mt], b_h[nt]);
                mma_bf16(acc[mt][nt], a_h[mt], b_l[nt]);
                mma_bf16(acc[mt][nt], a_h[mt], b_h[nt]);
            }
    }
    const float scale = 0.125f;
    #pragma unroll
    for (int mt = 0; mt < 2; mt++) {
        #pragma unroll
        for (int nt = 0; nt < 4; nt++) {
            int r0 = t0 + warpM * 32 + mt * 16 + (lane >> 2);
            int cb = s0 + warpN * 32 + nt * 8 + (lane & 3) * 2;
            #pragma unroll
            for (int half = 0; half < 2; half++) {
                int r = r0 + half * 8;
                float2 o = make_float2(acc[mt][nt][half * 2] * scale,
                                       acc[mt][nt][half * 2 + 1] * scale);
                *(float2*)(P + ((size_t)bh * Td + r) * Td + cb) = o;
            }
        }
    }
}

// ---------------- causal softmax per row (float4, smem buffer) --------------
__global__ __launch_bounds__(256) void softmax_k(float* __restrict__ P) {
    __shared__ float buf[Td];
    const size_t r = blockIdx.x;
    const int t = (int)(r & (Td - 1));
    float* row = P + r * Td;
    const int n = t + 1, n4 = n >> 2, tail = n4 * 4;
    float4* row4 = (float4*)row;
    float4* buf4 = (float4*)buf;
    float m = -INFINITY;
    for (int i = threadIdx.x; i < n4; i += 256) {
        float4 v = row4[i];
        buf4[i] = v;
        m = fmaxf(m, fmaxf(fmaxf(v.x, v.y), fmaxf(v.z, v.w)));
    }
    {
        int i = tail + threadIdx.x;
        if (i < n) { float v = row[i]; buf[i] = v; m = fmaxf(m, v); }
    }
    m = block_reduce_max(m);
    float s = 0.0f;
    for (int i = threadIdx.x; i < n4; i += 256) {
        float4 v = buf4[i];
        v.x = __expf(v.x - m); v.y = __expf(v.y - m);
        v.z = __expf(v.z - m); v.w = __expf(v.w - m);
        buf4[i] = v;
        s += v.x + v.y + v.z + v.w;
    }
    {
        int i = tail + threadIdx.x;
        if (i < n) { float e = __expf(buf[i] - m); buf[i] = e; s += e; }
    }
    s = block_reduce_sum(s);
    const float inv = 1.0f / s;
    for (int i = threadIdx.x; i < n4; i += 256) {
        float4 v = buf4[i];
        v.x *= inv; v.y *= inv; v.z *= inv; v.w *= inv;
        row4[i] = v;
    }
    {
        int i = tail + threadIdx.x;
        if (i < n) row[i] = buf[i] * inv;
    }
    const int fillEnd = ((t >> 6) << 6) + 64;
    for (int i = n + (int)threadIdx.x; i < fillEnd; i += 256) row[i] = 0.0f;
}

// ---------------- attn_mean ------------------------------------------------
__global__ __launch_bounds__(256) void attnmean_k(const float* __restrict__ P,
                                                  float* __restrict__ out) {
    const size_t i4 = (size_t)blockIdx.x * 256 + threadIdx.x;
    const int scol = (int)(i4 & (Td / 4 - 1)) * 4;
    const int t = (int)((i4 >> 9) & (Td - 1));
    const size_t off = (size_t)Hd * Td * Td;
    float4 o;
    if (scol > t) {
        o = make_float4(0.f, 0.f, 0.f, 0.f);
    } else {
        float4 a = *(const float4*)(P + i4 * 4);
        float4 b = *(const float4*)(P + i4 * 4 + off);
        o.x = 0.5f * (a.x + b.x); o.y = 0.5f * (a.y + b.y);
        o.z = 0.5f * (a.z + b.z); o.w = 0.5f * (a.w + b.w);
    }
    *(float4*)(out + i4 * 4) = o;
}

// ---------------- attn_out = P @ V (triangular), 3xBF16 --------------------
__global__ __launch_bounds__(128) void pv_tc(const float* __restrict__ P,
                                             const float* __restrict__ qkv,
                                             float* __restrict__ out) {
    const int bh = blockIdx.y;
    const int b = bh >> 4, h = bh & 15;
    const int t0 = blockIdx.x * 64;
    __shared__ uint32_t Ph[64][36], Pl[64][36];
    __shared__ uint32_t Vh[32][72], Vl[32][72];
    const int tid = threadIdx.x, lane = tid & 31, warp = tid >> 5;
    const int warpM = warp >> 1, warpN = warp & 1;
    float acc[2][4][4] = {};
    for (int s0 = 0; s0 <= t0; s0 += 64) {
        #pragma unroll
        for (int i = 0; i < 8; i++) {
            int idx = tid + i * 128;
            int r = idx >> 4, c4 = (idx & 15) * 4;
            float4 hi, lo;
            splitb4(*(const float4*)(P + ((size_t)bh * Td + t0 + r) * Td + s0 + c4), hi, lo);
            *(uint2*)&Ph[r][c4 >> 1] = make_uint2(packb(hi.x, hi.y), packb(hi.z, hi.w));
            *(uint2*)&Pl[r][c4 >> 1] = make_uint2(packb(lo.x, lo.y), packb(lo.z, lo.w));
        }
        #pragma unroll
        for (int i = 0; i < 4; i++) {
            int idx = tid + i * 128;
            int kkr = idx >> 4, n4 = (idx & 15) * 4;
            const float* vb = qkv + (size_t)(b * Td + s0) * QKVs + 2 * Cd + h * 64;
            float4 hA, lA, hB, lB;
            splitb4(*(const float4*)(vb + (size_t)(2 * kkr) * QKVs + n4), hA, lA);
            splitb4(*(const float4*)(vb + (size_t)(2 * kkr + 1) * QKVs + n4), hB, lB);
            *(uint4*)&Vh[kkr][n4] = make_uint4(packb(hA.x, hB.x), packb(hA.y, hB.y),
                                               packb(hA.z, hB.z), packb(hA.w, hB.w));
            *(uint4*)&Vl[kkr][n4] = make_uint4(packb(lA.x, lB.x), packb(lA.y, lB.y),
                                               packb(lA.z, lB.z), packb(lA.w, lB.w));
        }
        __syncthreads();
        #pragma unroll
        for (int ks = 0; ks < 4; ks++) {
            const int kb0 = ks * 8 + (lane & 3), fr = lane >> 2;
            uint32_t a_h[2][4], a_l[2][4], b_h[4][2], b_l[4][2];
            #pragma unroll
            for (int mt = 0; mt < 2; mt++) {
                int r = warpM * 32 + mt * 16 + fr;
                a_h[mt][0] = Ph[r][kb0];     a_h[mt][1] = Ph[r + 8][kb0];
                a_h[mt][2] = Ph[r][kb0 + 4]; a_h[mt][3] = Ph[r + 8][kb0 + 4];
                a_l[mt][0] = Pl[r][kb0];     a_l[mt][1] = Pl[r + 8][kb0];
                a_l[mt][2] = Pl[r][kb0 + 4]; a_l[mt][3] = Pl[r + 8][kb0 + 4];
            }
            #pragma unroll
            for (int nt = 0; nt < 4; nt++) {
                int n = warpN * 32 + nt * 8 + fr;
                b_h[nt][0] = Vh[kb0][n]; b_h[nt][1] = Vh[kb0 + 4][n];
                b_l[nt][0] = Vl[kb0][n]; b_l[nt][1] = Vl[kb0 + 4][n];
            }
            #pragma unroll
            for (int mt = 0; mt < 2; mt++)
                #pragma unroll
                for (int nt = 0; nt < 4; nt++) {
                    mma_bf16(acc[mt][nt], a_l[mt], b_h[nt]);
                    mma_bf16(acc[mt][nt], a_h[mt], b_l[nt]);
                    mma_bf16(acc[mt][nt], a_h[mt], b_h[nt]);
                }
        }
        __syncthreads();
    }
    #pragma unroll
    for (int mt = 0; mt < 2; mt++) {
        #pragma unroll
        for (int nt = 0; nt < 4; nt++) {
            int r0 = t0 + warpM * 32 + mt * 16 + (lane >> 2);
            int cb = warpN * 32 + nt * 8 + (lane & 3) * 2;
            #pragma unroll
            for (int half = 0; half < 2; half++) {
                int r = r0 + half * 8;
                float2 o = make_float2(acc[mt][nt][half * 2], acc[mt][nt][half * 2 + 1]);
                *(float2*)(out + (size_t)(b * Td + r) * Cd + h * 64 + cb) = o;
            }
        }
    }
}

// ---------------- launch ---------------------------------------------------
extern "C" void kernel_launch(void* const* d_in, const int* in_sizes, int n_in,
                              void* d_out, int out_size) {
    const float* x      = (const float*)d_in[0];
    const float* ln1_w  = (const float*)d_in[1];
    const float* ln1_b  = (const float*)d_in[2];
    const float* w_qkv  = (const float*)d_in[3];
    const float* b_qkv  = (const float*)d_in[4];
    const float* w_proj = (const float*)d_in[5];
    const float* b_proj = (const float*)d_in[6];
    const float* ln2_w  = (const float*)d_in[7];
    const float* ln2_b  = (const float*)d_in[8];
    const float* w_fc   = (const float*)d_in[9];
    const float* b_fc   = (const float*)d_in[10];
    const float* w_fc2  = (const float*)d_in[11];
    const float* b_fc2  = (const float*)d_in[12];

    float* out_x    = (float*)d_out;
    float* out_attn = (float*)d_out + (size_t)Rows * Cd;

    float *gh, *gqkv, *gP, *gattn, *gx1, *gfc;
    cudaGetSymbolAddress((void**)&gh,   g_h);
    cudaGetSymbolAddress((void**)&gqkv, g_qkv);
    cudaGetSymbolAddress((void**)&gP,   g_P);
    cudaGetSymbolAddress((void**)&gattn,g_attn);
    cudaGetSymbolAddress((void**)&gx1,  g_x1);
    cudaGetSymbolAddress((void**)&gfc,  g_fc);

    ln_k<<<Rows, 256>>>(x, ln1_w, ln1_b, gh);
    tgemm_k<0><<<dim3(QKVs / 128, Rows / 128), 256>>>(Rows, QKVs, Cd, gh, w_qkv, b_qkv, nullptr, gqkv);
    scores_tc<<<dim3(Td / 64, Td / 64, Bd * Hd), 128>>>(gqkv, gP);
    softmax_k<<<Bd * Hd * Td, 256>>>(gP);
    attnmean_k<<<(unsigned)((size_t)Hd * Td * Td / 4 / 256), 256>>>(gP, out_attn);
    pv_tc<<<dim3(Td / 64, Bd * Hd), 128>>>(gP, gqkv, gattn);
    tgemm_k<1><<<dim3(Cd / 128, Rows / 128), 256>>>(Rows, Cd, Cd, gattn, w_proj, b_proj, x, gx1);
    ln_k<<<Rows, 256>>>(gx1, ln2_w, ln2_b, gh);
    tgemm_k<2><<<dim3(4 * Cd / 128, Rows / 128), 256>>>(Rows, 4 * Cd, Cd, gh, w_fc, b_fc, nullptr, gfc);
    tgemm_k<1><<<dim3(Cd / 128, Rows / 128), 256>>>(Rows, Cd, 4 * Cd, gfc, w_fc2, b_fc2, gx1, out_x);
}

// round 12
// speedup vs baseline: 1.4015x; 1.0632x over previous
#include <cuda_runtime.h>
#include <cuda_bf16.h>
#include <math.h>
#include <stdint.h>

// Problem constants
constexpr int Bd = 2;
constexpr int Td = 2048;
constexpr int Cd = 1024;
constexpr int Hd = 16;
constexpr int Rows = Bd * Td;   // 4096
constexpr int QKVs = 3 * Cd;    // 3072

// ---------------- scratch (device globals) ---------------------------------
__device__ float g_h   [Rows * Cd];
__device__ float g_qkv [Rows * QKVs];
__device__ float g_P   [(size_t)Bd * Hd * Td * Td];
__device__ float g_attn[Rows * Cd];
__device__ float g_x1  [Rows * Cd];
__device__ float g_fc  [Rows * 4 * Cd];

// ---------------- bf16 mma m16n8k16 + split helpers ------------------------
__device__ __forceinline__ void mma_bf16(float* c, const uint32_t* a, const uint32_t* b) {
    asm volatile(
        "mma.sync.aligned.m16n8k16.row.col.f32.bf16.bf16.f32 "
        "{%0,%1,%2,%3}, {%4,%5,%6,%7}, {%8,%9}, {%0,%1,%2,%3};\n"
        : "+f"(c[0]), "+f"(c[1]), "+f"(c[2]), "+f"(c[3])
        : "r"(a[0]), "r"(a[1]), "r"(a[2]), "r"(a[3]), "r"(b[0]), "r"(b[1]));
}
__device__ __forceinline__ uint32_t packb(float even, float odd) {
    uint32_t r;
    asm("cvt.rn.bf16x2.f32 %0, %1, %2;" : "=r"(r) : "f"(odd), "f"(even));
    return r;
}
__device__ __forceinline__ void splitb(float x, float& hi, float& lo) {
    float h = __bfloat162float(__float2bfloat16_rn(x));
    hi = h; lo = x - h;
}
__device__ __forceinline__ void splitb4(float4 v, float4& hi, float4& lo) {
    splitb(v.x, hi.x, lo.x); splitb(v.y, hi.y, lo.y);
    splitb(v.z, hi.z, lo.z); splitb(v.w, hi.w, lo.w);
}
__device__ __forceinline__ void ldsm_x4(uint32_t* r, uint32_t addr) {
    asm volatile("ldmatrix.sync.aligned.m8n8.x4.shared.b16 {%0,%1,%2,%3}, [%4];"
                 : "=r"(r[0]), "=r"(r[1]), "=r"(r[2]), "=r"(r[3]) : "r"(addr));
}

// ---------------- block reductions -----------------------------------------
__device__ __forceinline__ float block_reduce_sum(float v) {
    __shared__ float sm[32];
    int lane = threadIdx.x & 31, wid = threadIdx.x >> 5;
    #pragma unroll
    for (int o = 16; o; o >>= 1) v += __shfl_down_sync(0xffffffffu, v, o);
    if (lane == 0) sm[wid] = v;
    __syncthreads();
    float r;
    if (wid == 0) {
        float t = (lane < 8) ? sm[lane] : 0.0f;
        #pragma unroll
        for (int o = 4; o; o >>= 1) t += __shfl_down_sync(0xffu, t, o);
        if (lane == 0) sm[0] = t;
    }
    __syncthreads();
    r = sm[0];
    __syncthreads();
    return r;
}
__device__ __forceinline__ float block_reduce_max(float v) {
    __shared__ float sm[32];
    int lane = threadIdx.x & 31, wid = threadIdx.x >> 5;
    #pragma unroll
    for (int o = 16; o; o >>= 1) v = fmaxf(v, __shfl_down_sync(0xffffffffu, v, o));
    if (lane == 0) sm[wid] = v;
    __syncthreads();
    float r;
    if (wid == 0) {
        float t = (lane < 8) ? sm[lane] : -INFINITY;
        #pragma unroll
        for (int o = 4; o; o >>= 1) t = fmaxf(t, __shfl_down_sync(0xffu, t, o));
        if (lane == 0) sm[0] = t;
    }
    __syncthreads();
    r = sm[0];
    __syncthreads();
    return r;
}

// ---------------- LayerNorm ------------------------------------------------
__global__ __launch_bounds__(256) void ln_k(const float* __restrict__ x,
                                            const float* __restrict__ w,
                                            const float* __restrict__ b,
                                            float* __restrict__ y) {
    const int row = blockIdx.x;
    const float* xr = x + (size_t)row * Cd;
    float4 v = *(const float4*)(xr + threadIdx.x * 4);
    float s  = v.x + v.y + v.z + v.w;
    float sq = v.x * v.x + v.y * v.y + v.z * v.z + v.w * v.w;
    float sum  = block_reduce_sum(s);
    float sumq = block_reduce_sum(sq);
    float mean = sum * (1.0f / Cd);
    float var  = sumq * (1.0f / Cd) - mean * mean;
    float rstd = rsqrtf(var + 1e-5f);
    int c = threadIdx.x * 4;
    float4 wv = *(const float4*)(w + c);
    float4 bv = *(const float4*)(b + c);
    float4 o;
    o.x = (v.x - mean) * rstd * wv.x + bv.x;
    o.y = (v.y - mean) * rstd * wv.y + bv.y;
    o.z = (v.z - mean) * rstd * wv.z + bv.z;
    o.w = (v.w - mean) * rstd * wv.w + bv.w;
    *(float4*)(y + (size_t)row * Cd + c) = o;
}

// ---------------- 3xBF16 GEMM (R11: LDSM A-fragments) ----------------------
template <int EPI>
__global__ __launch_bounds__(256) void tgemm_k(int M, int N, int K,
                                               const float* __restrict__ A,
                                               const float* __restrict__ B,
                                               const float* __restrict__ bias,
                                               const float* __restrict__ res,
                                               float* __restrict__ C) {
    constexpr int BK = 16;
    __shared__ uint32_t Ah[128][12], Al[128][12];
    __shared__ uint32_t Bh[8][136],  Bl[8][136];
    const int tid = threadIdx.x, lane = tid & 31, warp = tid >> 5;
    const int warpM = warp >> 2, warpN = warp & 3;
    const size_t bM = (size_t)blockIdx.y * 128, bN = (size_t)blockIdx.x * 128;

    const int aRow = tid >> 2, aC = (tid & 3) * 4;
    const int bK = warp * 2;
    const int bCol = lane * 4;

    const uint32_t aHbase = (uint32_t)__cvta_generic_to_shared(&Ah[0][0]);
    const uint32_t aLbase = (uint32_t)__cvta_generic_to_shared(&Al[0][0]);
    const int ldsmRow = (lane & 15), ldsmCol = (lane >> 4) * 4;

    float4 ra[2], rba, rbb;
    #pragma unroll
    for (int i = 0; i < 2; i++)
        ra[i] = *(const float4*)(A + (bM + aRow + 64 * i) * (size_t)K + aC);
    rba = *(const float4*)(B + (size_t)bK * N + bN + bCol);
    rbb = *(const float4*)(B + (size_t)(bK + 1) * N + bN + bCol);

    float acc[4][4][4] = {};
    for (int k0 = 0; k0 < K; k0 += BK) {
        #pragma unroll
        for (int i = 0; i < 2; i++) {
            float4 hi, lo;
            splitb4(ra[i], hi, lo);
            *(uint2*)&Ah[aRow + 64 * i][(tid & 3) * 2] =
                make_uint2(packb(hi.x, hi.y), packb(hi.z, hi.w));
            *(uint2*)&Al[aRow + 64 * i][(tid & 3) * 2] =
                make_uint2(packb(lo.x, lo.y), packb(lo.z, lo.w));
        }
        {
            float4 ha, la, hb, lb;
            splitb4(rba, ha, la);
            splitb4(rbb, hb, lb);
            *(uint4*)&Bh[warp][bCol] = make_uint4(packb(ha.x, hb.x), packb(ha.y, hb.y),
                                                  packb(ha.z, hb.z), packb(ha.w, hb.w));
            *(uint4*)&Bl[warp][bCol] = make_uint4(packb(la.x, lb.x), packb(la.y, lb.y),
                                                  packb(la.z, lb.z), packb(la.w, lb.w));
        }
        __syncthreads();
        if (k0 + BK < K) {
            #pragma unroll
            for (int i = 0; i < 2; i++)
                ra[i] = *(const float4*)(A + (bM + aRow + 64 * i) * (size_t)K + k0 + BK + aC);
            rba = *(const float4*)(B + (size_t)(k0 + BK + bK) * N + bN + bCol);
            rbb = *(const float4*)(B + (size_t)(k0 + BK + bK + 1) * N + bN + bCol);
        }
        uint32_t a_h[4][4], a_l[4][4], b_h[4][2], b_l[4][2];
        const int kk = lane & 3, fr = lane >> 2;
        #pragma unroll
        for (int mt = 0; mt < 4; mt++) {
            int r = warpM * 64 + mt * 16 + ldsmRow;
            ldsm_x4(a_h[mt], aHbase + (uint32_t)(r * 12 + ldsmCol) * 4u);
            ldsm_x4(a_l[mt], aLbase + (uint32_t)(r * 12 + ldsmCol) * 4u);
        }
        #pragma unroll
        for (int nt = 0; nt < 4; nt++) {
            int n = warpN * 32 + nt * 8 + fr;
            b_h[nt][0] = Bh[kk][n]; b_h[nt][1] = Bh[kk + 4][n];
            b_l[nt][0] = Bl[kk][n]; b_l[nt][1] = Bl[kk + 4][n];
        }
        #pragma unroll
        for (int mt = 0; mt < 4; mt++)
            #pragma unroll
            for (int nt = 0; nt < 4; nt++) {
                mma_bf16(acc[mt][nt], a_l[mt], b_h[nt]);
                mma_bf16(acc[mt][nt], a_h[mt], b_l[nt]);
                mma_bf16(acc[mt][nt], a_h[mt], b_h[nt]);
            }
        __syncthreads();
    }
    #pragma unroll
    for (int mt = 0; mt < 4; mt++) {
        #pragma unroll
        for (int nt = 0; nt < 4; nt++) {
            size_t r0 = bM + warpM * 64 + mt * 16 + (lane >> 2);
            size_t cb = bN + warpN * 32 + nt * 8 + (lane & 3) * 2;
            float b0 = bias[cb], b1 = bias[cb + 1];
            #pragma unroll
            for (int half = 0; half < 2; half++) {
                size_t r = r0 + half * 8;
                float v0 = acc[mt][nt][half * 2 + 0] + b0;
                float v1 = acc[mt][nt][half * 2 + 1] + b1;
                if (EPI == 1) {
                    const float* rp = res + r * N + cb;
                    v0 += rp[0]; v1 += rp[1];
                }
                if (EPI == 2) {
                    v0 = 0.5f * v0 * (1.0f + erff(v0 * 0.70710678118654752f));
                    v1 = 0.5f * v1 * (1.0f + erff(v1 * 0.70710678118654752f));
                }
                *(float2*)(C + r * N + cb) = make_float2(v0, v1);
            }
        }
    }
}

// ---------------- scores: S = Q K^T * scale, LDSM Q + K --------------------
__global__ __launch_bounds__(128) void scores_tc(const float* __restrict__ qkv,
                                                 float* __restrict__ P) {
    const int bh = blockIdx.z;
    const int b = bh >> 4, h = bh & 15;
    const int t0 = blockIdx.y * 64, s0 = blockIdx.x * 64;
    if (s0 > t0) return;
    __shared__ uint32_t Qh[64][36], Ql[64][36];
    __shared__ uint32_t Kh[64][36], Kl[64][36];
    const int tid = threadIdx.x, lane = tid & 31, warp = tid >> 5;
    const int warpM = warp >> 1, warpN = warp & 1;
    const float* qb = qkv + (size_t)(b * Td + t0) * QKVs + h * 64;
    const float* kb = qkv + (size_t)(b * Td + s0) * QKVs + Cd + h * 64;
    #pragma unroll
    for (int i = 0; i < 8; i++) {
        int idx = tid + i * 128;
        int r = idx >> 4, c4 = (idx & 15) * 4;
        float4 hi, lo;
        splitb4(*(const float4*)(qb + (size_t)r * QKVs + c4), hi, lo);
        *(uint2*)&Qh[r][c4 >> 1] = make_uint2(packb(hi.x, hi.y), packb(hi.z, hi.w));
        *(uint2*)&Ql[r][c4 >> 1] = make_uint2(packb(lo.x, lo.y), packb(lo.z, lo.w));
        splitb4(*(const float4*)(kb + (size_t)r * QKVs + c4), hi, lo);
        *(uint2*)&Kh[r][c4 >> 1] = make_uint2(packb(hi.x, hi.y), packb(hi.z, hi.w));
        *(uint2*)&Kl[r][c4 >> 1] = make_uint2(packb(lo.x, lo.y), packb(lo.z, lo.w));
    }
    __syncthreads();
    const uint32_t qH = (uint32_t)__cvta_generic_to_shared(&Qh[0][0]);
    const uint32_t qL = (uint32_t)__cvta_generic_to_shared(&Ql[0][0]);
    const uint32_t kH = (uint32_t)__cvta_generic_to_shared(&Kh[0][0]);
    const uint32_t kL = (uint32_t)__cvta_generic_to_shared(&Kl[0][0]);
    const int ldsmRow = lane & 15, ldsmCol = (lane >> 4) * 4;
    // B-ldsm address: quad q=lane>>3: matrices {nt=2p+ (q>>1)}, col (q&1)*4
    const int bRowOff = ((lane >> 4) & 1) * 8 + (lane & 7);   // nt-half row
    const int bColOff = ((lane >> 3) & 1) * 4;
    float acc[2][4][4] = {};
    #pragma unroll
    for (int ks = 0; ks < 4; ks++) {
        uint32_t a_h[2][4], a_l[2][4], b_h[4][2], b_l[4][2];
        #pragma unroll
        for (int mt = 0; mt < 2; mt++) {
            int r = warpM * 32 + mt * 16 + ldsmRow;
            uint32_t off = (uint32_t)(r * 36 + ks * 8 + ldsmCol) * 4u;
            ldsm_x4(a_h[mt], qH + off);
            ldsm_x4(a_l[mt], qL + off);
        }
        #pragma unroll
        for (int p = 0; p < 2; p++) {   // nt pairs (2p, 2p+1)
            int n = warpN * 32 + p * 16 + bRowOff;
            uint32_t off = (uint32_t)(n * 36 + ks * 8 + bColOff) * 4u;
            uint32_t dh[4], dl[4];
            ldsm_x4(dh, kH + off);
            ldsm_x4(dl, kL + off);
            b_h[2 * p][0] = dh[0]; b_h[2 * p][1] = dh[1];
            b_h[2 * p + 1][0] = dh[2]; b_h[2 * p + 1][1] = dh[3];
            b_l[2 * p][0] = dl[0]; b_l[2 * p][1] = dl[1];
            b_l[2 * p + 1][0] = dl[2]; b_l[2 * p + 1][1] = dl[3];
        }
        #pragma unroll
        for (int mt = 0; mt < 2; mt++)
            #pragma unroll
            for (int nt = 0; nt < 4; nt++) {
                mma_bf16(acc[mt][nt], a_l[mt], b_h[nt]);
                mma_bf16(acc[mt][nt], a_h[mt], b_l[nt]);
                mma_bf16(acc[mt][nt], a_h[mt], b_h[nt]);
            }
    }
    const float scale = 0.125f;
    #pragma unroll
    for (int mt = 0; mt < 2; mt++) {
        #pragma unroll
        for (int nt = 0; nt < 4; nt++) {
            int r0 = t0 + warpM * 32 + mt * 16 + (lane >> 2);
            int cb = s0 + warpN * 32 + nt * 8 + (lane & 3) * 2;
            #pragma unroll
            for (int half = 0; half < 2; half++) {
                int r = r0 + half * 8;
                float2 o = make_float2(acc[mt][nt][half * 2] * scale,
                                       acc[mt][nt][half * 2 + 1] * scale);
                *(float2*)(P + ((size_t)bh * Td + r) * Td + cb) = o;
            }
        }
    }
}

// ---------------- fused softmax (both batches) + mean ----------------------
__global__ __launch_bounds__(256) void softmean_k(float* __restrict__ P,
                                                  float* __restrict__ outm) {
    __shared__ float bufA[Td], bufB[Td];
    const int ht = blockIdx.x;
    const int t = ht & (Td - 1), h = ht >> 11;
    float* r0 = P + ((size_t)h * Td + t) * Td;                    // b=0
    float* r1 = r0 + (size_t)Hd * Td * Td;                        // b=1
    float* rm = outm + ((size_t)h * Td + t) * Td;
    const int n = t + 1, n4 = n >> 2, tail = n4 * 4;
    float4* r04 = (float4*)r0; float4* r14 = (float4*)r1; float4* rm4 = (float4*)rm;
    float4* bA4 = (float4*)bufA; float4* bB4 = (float4*)bufB;
    float m0 = -INFINITY, m1 = -INFINITY;
    for (int i = threadIdx.x; i < n4; i += 256) {
        float4 v0 = r04[i]; bA4[i] = v0;
        m0 = fmaxf(m0, fmaxf(fmaxf(v0.x, v0.y), fmaxf(v0.z, v0.w)));
        float4 v1 = r14[i]; bB4[i] = v1;
        m1 = fmaxf(m1, fmaxf(fmaxf(v1.x, v1.y), fmaxf(v1.z, v1.w)));
    }
    {
        int i = tail + threadIdx.x;
        if (i < n) {
            float v0 = r0[i]; bufA[i] = v0; m0 = fmaxf(m0, v0);
            float v1 = r1[i]; bufB[i] = v1; m1 = fmaxf(m1, v1);
        }
    }
    m0 = block_reduce_max(m0);
    m1 = block_reduce_max(m1);
    float s0 = 0.0f, s1 = 0.0f;
    for (int i = threadIdx.x; i < n4; i += 256) {
        float4 v0 = bA4[i];
        v0.x = __expf(v0.x - m0); v0.y = __expf(v0.y - m0);
        v0.z = __expf(v0.z - m0); v0.w = __expf(v0.w - m0);
        bA4[i] = v0; s0 += v0.x + v0.y + v0.z + v0.w;
        float4 v1 = bB4[i];
        v1.x = __expf(v1.x - m1); v1.y = __expf(v1.y - m1);
        v1.z = __expf(v1.z - m1); v1.w = __expf(v1.w - m1);
        bB4[i] = v1; s1 += v1.x + v1.y + v1.z + v1.w;
    }
    {
        int i = tail + threadIdx.x;
        if (i < n) {
            float e0 = __expf(bufA[i] - m0); bufA[i] = e0; s0 += e0;
            float e1 = __expf(bufB[i] - m1); bufB[i] = e1; s1 += e1;
        }
    }
    s0 = block_reduce_sum(s0);
    s1 = block_reduce_sum(s1);
    const float i0 = 1.0f / s0, i1 = 1.0f / s1;
    for (int i = threadIdx.x; i < n4; i += 256) {
        float4 v0 = bA4[i];
        v0.x *= i0; v0.y *= i0; v0.z *= i0; v0.w *= i0;
        r04[i] = v0;
        float4 v1 = bB4[i];
        v1.x *= i1; v1.y *= i1; v1.z *= i1; v1.w *= i1;
        r14[i] = v1;
        float4 mm;
        mm.x = 0.5f * (v0.x + v1.x); mm.y = 0.5f * (v0.y + v1.y);
        mm.z = 0.5f * (v0.z + v1.z); mm.w = 0.5f * (v0.w + v1.w);
        rm4[i] = mm;
    }
    {
        int i = tail + threadIdx.x;
        if (i < n) {
            float v0 = bufA[i] * i0; r0[i] = v0;
            float v1 = bufB[i] * i1; r1[i] = v1;
            rm[i] = 0.5f * (v0 + v1);
        }
    }
    const int fillEnd = ((t >> 6) << 6) + 64;
    for (int i = n + (int)threadIdx.x; i < fillEnd; i += 256) { r0[i] = 0.0f; r1[i] = 0.0f; }
    for (int i = n + (int)threadIdx.x; i < Td; i += 256) rm[i] = 0.0f;
}

// ---------------- attn_out = P @ V (triangular), LDSM P --------------------
__global__ __launch_bounds__(128) void pv_tc(const float* __restrict__ P,
                                             const float* __restrict__ qkv,
                                             float* __restrict__ out) {
    const int bh = blockIdx.y;
    const int b = bh >> 4, h = bh & 15;
    const int t0 = blockIdx.x * 64;
    __shared__ uint32_t Ph[64][36], Pl[64][36];
    __shared__ uint32_t Vh[32][72], Vl[32][72];
    const int tid = threadIdx.x, lane = tid & 31, warp = tid >> 5;
    const int warpM = warp >> 1, warpN = warp & 1;
    const uint32_t pH = (uint32_t)__cvta_generic_to_shared(&Ph[0][0]);
    const uint32_t pL = (uint32_t)__cvta_generic_to_shared(&Pl[0][0]);
    const int ldsmRow = lane & 15, ldsmCol = (lane >> 4) * 4;
    float acc[2][4][4] = {};
    for (int s0 = 0; s0 <= t0; s0 += 64) {
        #pragma unroll
        for (int i = 0; i < 8; i++) {
            int idx = tid + i * 128;
            int r = idx >> 4, c4 = (idx & 15) * 4;
            float4 hi, lo;
            splitb4(*(const float4*)(P + ((size_t)bh * Td + t0 + r) * Td + s0 + c4), hi, lo);
            *(uint2*)&Ph[r][c4 >> 1] = make_uint2(packb(hi.x, hi.y), packb(hi.z, hi.w));
            *(uint2*)&Pl[r][c4 >> 1] = make_uint2(packb(lo.x, lo.y), packb(lo.z, lo.w));
        }
        #pragma unroll
        for (int i = 0; i < 4; i++) {
            int idx = tid + i * 128;
            int kkr = idx >> 4, n4 = (idx & 15) * 4;
            const float* vb = qkv + (size_t)(b * Td + s0) * QKVs + 2 * Cd + h * 64;
            float4 hA, lA, hB, lB;
            splitb4(*(const float4*)(vb + (size_t)(2 * kkr) * QKVs + n4), hA, lA);
            splitb4(*(const float4*)(vb + (size_t)(2 * kkr + 1) * QKVs + n4), hB, lB);
            *(uint4*)&Vh[kkr][n4] = make_uint4(packb(hA.x, hB.x), packb(hA.y, hB.y),
                                               packb(hA.z, hB.z), packb(hA.w, hB.w));
            *(uint4*)&Vl[kkr][n4] = make_uint4(packb(lA.x, lB.x), packb(lA.y, lB.y),
                                               packb(lA.z, lB.z), packb(lA.w, lB.w));
        }
        __syncthreads();
        #pragma unroll
        for (int ks = 0; ks < 4; ks++) {
            const int kb0 = ks * 8 + (lane & 3), fr = lane >> 2;
            uint32_t a_h[2][4], a_l[2][4], b_h[4][2], b_l[4][2];
            #pragma unroll
            for (int mt = 0; mt < 2; mt++) {
                int r = warpM * 32 + mt * 16 + ldsmRow;
                uint32_t off = (uint32_t)(r * 36 + ks * 8 + ldsmCol) * 4u;
                ldsm_x4(a_h[mt], pH + off);
                ldsm_x4(a_l[mt], pL + off);
            }
            #pragma unroll
            for (int nt = 0; nt < 4; nt++) {
                int n = warpN * 32 + nt * 8 + fr;
                b_h[nt][0] = Vh[kb0][n]; b_h[nt][1] = Vh[kb0 + 4][n];
                b_l[nt][0] = Vl[kb0][n]; b_l[nt][1] = Vl[kb0 + 4][n];
            }
            #pragma unroll
            for (int mt = 0; mt < 2; mt++)
                #pragma unroll
                for (int nt = 0; nt < 4; nt++) {
                    mma_bf16(acc[mt][nt], a_l[mt], b_h[nt]);
                    mma_bf16(acc[mt][nt], a_h[mt], b_l[nt]);
                    mma_bf16(acc[mt][nt], a_h[mt], b_h[nt]);
                }
        }
        __syncthreads();
    }
    #pragma unroll
    for (int mt = 0; mt < 2; mt++) {
        #pragma unroll
        for (int nt = 0; nt < 4; nt++) {
            int r0 = t0 + warpM * 32 + mt * 16 + (lane >> 2);
            int cb = warpN * 32 + nt * 8 + (lane & 3) * 2;
            #pragma unroll
            for (int half = 0; half < 2; half++) {
                int r = r0 + half * 8;
                float2 o = make_float2(acc[mt][nt][half * 2], acc[mt][nt][half * 2 + 1]);
                *(float2*)(out + (size_t)(b * Td + r) * Cd + h * 64 + cb) = o;
            }
        }
    }
}

// ---------------- launch ---------------------------------------------------
extern "C" void kernel_launch(void* const* d_in, const int* in_sizes, int n_in,
                              void* d_out, int out_size) {
    const float* x      = (const float*)d_in[0];
    const float* ln1_w  = (const float*)d_in[1];
    const float* ln1_b  = (const float*)d_in[2];
    const float* w_qkv  = (const float*)d_in[3];
    const float* b_qkv  = (const float*)d_in[4];
    const float* w_proj = (const float*)d_in[5];
    const float* b_proj = (const float*)d_in[6];
    const float* ln2_w  = (const float*)d_in[7];
    const float* ln2_b  = (const float*)d_in[8];
    const float* w_fc   = (const float*)d_in[9];
    const float* b_fc   = (const float*)d_in[10];
    const float* w_fc2  = (const float*)d_in[11];
    const float* b_fc2  = (const float*)d_in[12];

    float* out_x    = (float*)d_out;
    float* out_attn = (float*)d_out + (size_t)Rows * Cd;

    float *gh, *gqkv, *gP, *gattn, *gx1, *gfc;
    cudaGetSymbolAddress((void**)&gh,   g_h);
    cudaGetSymbolAddress((void**)&gqkv, g_qkv);
    cudaGetSymbolAddress((void**)&gP,   g_P);
    cudaGetSymbolAddress((void**)&gattn,g_attn);
    cudaGetSymbolAddress((void**)&gx1,  g_x1);
    cudaGetSymbolAddress((void**)&gfc,  g_fc);

    ln_k<<<Rows, 256>>>(x, ln1_w, ln1_b, gh);
    tgemm_k<0><<<dim3(QKVs / 128, Rows / 128), 256>>>(Rows, QKVs, Cd, gh, w_qkv, b_qkv, nullptr, gqkv);
    scores_tc<<<dim3(Td / 64, Td / 64, Bd * Hd), 128>>>(gqkv, gP);
    softmean_k<<<Hd * Td, 256>>>(gP, out_attn);
    pv_tc<<<dim3(Td / 64, Bd * Hd), 128>>>(gP, gqkv, gattn);
    tgemm_k<1><<<dim3(Cd / 128, Rows / 128), 256>>>(Rows, Cd, Cd, gattn, w_proj, b_proj, x, gx1);
    ln_k<<<Rows, 256>>>(gx1, ln2_w, ln2_b, gh);
    tgemm_k<2><<<dim3(4 * Cd / 128, Rows / 128), 256>>>(Rows, 4 * Cd, Cd, gh, w_fc, b_fc, nullptr, gfc);
    tgemm_k<1><<<dim3(Cd / 128, Rows / 128), 256>>>(Rows, Cd, 4 * Cd, gfc, w_fc2, b_fc2, gx1, out_x);
}